// round 1
// baseline (speedup 1.0000x reference)
#include <cuda_runtime.h>

// Problem constants (fixed shapes)
#define BB 2
#define NN 2048
#define CC 1024
#define HH 16
#define HD 64
#define MM (BB * NN)   // 4096 rows

// Scratch (device globals — no allocations allowed)
__device__ float g_xn[MM * CC];        // LN1 output
__device__ float g_qk[MM * 2 * CC];    // qk projection
__device__ float g_v[MM * CC];         // v projection
__device__ float g_ao[MM * CC];        // attention output
__device__ float g_l2[MM * CC];        // LN2 output

// ---------------------------------------------------------------------------
// LayerNorm: one block per row, 256 threads, C=1024 -> one float4 per thread
// ---------------------------------------------------------------------------
__global__ void ln_kernel(const float* __restrict__ x,
                          const float* __restrict__ g,
                          const float* __restrict__ b,
                          float* __restrict__ out) {
    int row = blockIdx.x;
    int t = threadIdx.x;  // 256
    const float4* xr = reinterpret_cast<const float4*>(x + (size_t)row * CC);
    float4 v = xr[t];
    float s  = v.x + v.y + v.z + v.w;
    float ss = v.x * v.x + v.y * v.y + v.z * v.z + v.w * v.w;

    // block reduce (8 warps)
    #pragma unroll
    for (int o = 16; o > 0; o >>= 1) {
        s  += __shfl_down_sync(0xFFFFFFFFu, s,  o);
        ss += __shfl_down_sync(0xFFFFFFFFu, ss, o);
    }
    __shared__ float sh[8][2];
    int w = t >> 5, l = t & 31;
    if (l == 0) { sh[w][0] = s; sh[w][1] = ss; }
    __syncthreads();
    if (w == 0) {
        s  = (l < 8) ? sh[l][0] : 0.0f;
        ss = (l < 8) ? sh[l][1] : 0.0f;
        #pragma unroll
        for (int o = 4; o > 0; o >>= 1) {
            s  += __shfl_down_sync(0xFFFFFFFFu, s,  o);
            ss += __shfl_down_sync(0xFFFFFFFFu, ss, o);
        }
        if (l == 0) { sh[0][0] = s; sh[0][1] = ss; }
    }
    __syncthreads();
    s = sh[0][0]; ss = sh[0][1];

    float mu  = s * (1.0f / CC);
    float var = ss * (1.0f / CC) - mu * mu;
    float inv = rsqrtf(var + 1e-5f);

    const float4 gv = reinterpret_cast<const float4*>(g)[t];
    const float4 bv = reinterpret_cast<const float4*>(b)[t];
    float4 o;
    o.x = (v.x - mu) * inv * gv.x + bv.x;
    o.y = (v.y - mu) * inv * gv.y + bv.y;
    o.z = (v.z - mu) * inv * gv.z + bv.z;
    o.w = (v.w - mu) * inv * gv.w + bv.w;
    reinterpret_cast<float4*>(out + (size_t)row * CC)[t] = o;
}

// ---------------------------------------------------------------------------
// Tiled SGEMM: C[M,N] = A[M,K] @ B[K,N] (+ bias). 64x64x16 tile, 256 threads,
// 4x4 register microtile per thread. All dims multiples of 64.
// ---------------------------------------------------------------------------
template <bool BIAS>
__global__ void gemm_kernel(const float* __restrict__ A,
                            const float* __restrict__ B,
                            const float* __restrict__ bias,
                            float* __restrict__ C,
                            int M, int N, int K) {
    __shared__ float As[16][64];  // [k][m]
    __shared__ float Bs[16][64];  // [k][n]

    int bx = blockIdx.x;          // N tile
    int by = blockIdx.y;          // M tile
    int tid = threadIdx.x;        // 256
    int tx = tid & 15, ty = tid >> 4;

    const int arow  = tid >> 2;         // 0..63
    const int acol4 = (tid & 3) * 4;    // 0,4,8,12
    const int brow  = tid >> 4;         // 0..15
    const int bcol4 = (tid & 15) * 4;   // 0..60

    float acc[4][4] = {};

    const float* Ab = A + (size_t)(by * 64 + arow) * K + acol4;
    const float* Bb = B + (size_t)brow * N + bx * 64 + bcol4;

    for (int k0 = 0; k0 < K; k0 += 16) {
        float4 a  = *reinterpret_cast<const float4*>(Ab + k0);
        float4 bb = *reinterpret_cast<const float4*>(Bb + (size_t)k0 * N);
        As[acol4 + 0][arow] = a.x;
        As[acol4 + 1][arow] = a.y;
        As[acol4 + 2][arow] = a.z;
        As[acol4 + 3][arow] = a.w;
        *reinterpret_cast<float4*>(&Bs[brow][bcol4]) = bb;
        __syncthreads();

        #pragma unroll
        for (int kk = 0; kk < 16; kk++) {
            float4 av = *reinterpret_cast<const float4*>(&As[kk][ty * 4]);
            float4 bv = *reinterpret_cast<const float4*>(&Bs[kk][tx * 4]);
            acc[0][0] += av.x * bv.x; acc[0][1] += av.x * bv.y;
            acc[0][2] += av.x * bv.z; acc[0][3] += av.x * bv.w;
            acc[1][0] += av.y * bv.x; acc[1][1] += av.y * bv.y;
            acc[1][2] += av.y * bv.z; acc[1][3] += av.y * bv.w;
            acc[2][0] += av.z * bv.x; acc[2][1] += av.z * bv.y;
            acc[2][2] += av.z * bv.z; acc[2][3] += av.z * bv.w;
            acc[3][0] += av.w * bv.x; acc[3][1] += av.w * bv.y;
            acc[3][2] += av.w * bv.z; acc[3][3] += av.w * bv.w;
        }
        __syncthreads();
    }

    int crow = by * 64 + ty * 4;
    int ccol = bx * 64 + tx * 4;
    float4 bias4 = make_float4(0.f, 0.f, 0.f, 0.f);
    if (BIAS) bias4 = *reinterpret_cast<const float4*>(bias + ccol);
    #pragma unroll
    for (int i = 0; i < 4; i++) {
        float4 r;
        r.x = acc[i][0] + bias4.x;
        r.y = acc[i][1] + bias4.y;
        r.z = acc[i][2] + bias4.z;
        r.w = acc[i][3] + bias4.w;
        *reinterpret_cast<float4*>(C + (size_t)(crow + i) * N + ccol) = r;
    }
}

// ---------------------------------------------------------------------------
// fp32 flash attention. BQ=64 queries per block, BK=32 keys per iter,
// 128 threads: thread t owns query row t>>1 and hd-half (t&1)*32 (32 accs).
// ---------------------------------------------------------------------------
__global__ void attn_kernel(const float* __restrict__ qk,
                            const float* __restrict__ vb,
                            float* __restrict__ out) {
    const int BQ = 64, BKT = 32;
    __shared__ float Qs[BQ][HD + 4];    // padded: stride 68 kills bank conflicts
    __shared__ float Ks[BKT][HD];
    __shared__ float Vs[BKT][HD];
    __shared__ float Ss[BQ][BKT + 1];   // padded: stride 33
    __shared__ float m_s[BQ], l_s[BQ], alpha_s[BQ];

    int qt = blockIdx.x, h = blockIdx.y, b = blockIdx.z;
    int tid = threadIdx.x;              // 128
    int qr = tid >> 1;
    int dh = (tid & 1) * 32;
    const float scale = 0.125f;         // hd^-0.5 = 64^-0.5

    float acc[32];
    #pragma unroll
    for (int d = 0; d < 32; d++) acc[d] = 0.0f;

    // load Q tile: 64 rows x 64 cols (q lives at col h*64+d of qk row)
    for (int i = tid; i < BQ * 16; i += 128) {
        int r = i >> 4, c4 = (i & 15) * 4;
        *reinterpret_cast<float4*>(&Qs[r][c4]) =
            *reinterpret_cast<const float4*>(
                qk + (size_t)(b * NN + qt * 64 + r) * (2 * CC) + h * HD + c4);
    }
    if (tid < BQ) { m_s[tid] = -1e30f; l_s[tid] = 0.0f; }
    __syncthreads();

    for (int k0 = 0; k0 < NN; k0 += BKT) {
        // load K (col CC + h*64 + d of qk row) and V tiles
        for (int i = tid; i < BKT * 16; i += 128) {
            int r = i >> 4, c4 = (i & 15) * 4;
            size_t grow = (size_t)(b * NN + k0 + r);
            *reinterpret_cast<float4*>(&Ks[r][c4]) =
                *reinterpret_cast<const float4*>(qk + grow * (2 * CC) + CC + h * HD + c4);
            *reinterpret_cast<float4*>(&Vs[r][c4]) =
                *reinterpret_cast<const float4*>(vb + grow * CC + h * HD + c4);
        }
        __syncthreads();

        // scores: thread computes S[qr][c0 .. c0+16)
        {
            int c0 = (tid & 1) * 16;
            float sacc[16];
            #pragma unroll
            for (int c = 0; c < 16; c++) sacc[c] = 0.0f;
            #pragma unroll
            for (int d0 = 0; d0 < HD; d0 += 16) {
                float4 q0 = *reinterpret_cast<const float4*>(&Qs[qr][d0 + 0]);
                float4 q1 = *reinterpret_cast<const float4*>(&Qs[qr][d0 + 4]);
                float4 q2 = *reinterpret_cast<const float4*>(&Qs[qr][d0 + 8]);
                float4 q3 = *reinterpret_cast<const float4*>(&Qs[qr][d0 + 12]);
                #pragma unroll
                for (int c = 0; c < 16; c++) {
                    const float4* kr = reinterpret_cast<const float4*>(&Ks[c0 + c][d0]);
                    float4 k0v = kr[0], k1v = kr[1], k2v = kr[2], k3v = kr[3];
                    float s = q0.x * k0v.x + q0.y * k0v.y + q0.z * k0v.z + q0.w * k0v.w;
                    s += q1.x * k1v.x + q1.y * k1v.y + q1.z * k1v.z + q1.w * k1v.w;
                    s += q2.x * k2v.x + q2.y * k2v.y + q2.z * k2v.z + q2.w * k2v.w;
                    s += q3.x * k3v.x + q3.y * k3v.y + q3.z * k3v.z + q3.w * k3v.w;
                    sacc[c] += s;
                }
            }
            #pragma unroll
            for (int c = 0; c < 16; c++) Ss[qr][c0 + c] = sacc[c] * scale;
        }
        __syncthreads();

        // online softmax row update (threads 0..63 each own one row)
        if (tid < BQ) {
            float m_old = m_s[tid];
            float mx = m_old;
            #pragma unroll
            for (int c = 0; c < BKT; c++) mx = fmaxf(mx, Ss[tid][c]);
            float alpha = __expf(m_old - mx);
            float l = l_s[tid] * alpha;
            #pragma unroll
            for (int c = 0; c < BKT; c++) {
                float p = __expf(Ss[tid][c] - mx);
                Ss[tid][c] = p;
                l += p;
            }
            alpha_s[tid] = alpha;
            m_s[tid] = mx;
            l_s[tid] = l;
        }
        __syncthreads();

        // rescale accumulators and add P @ V
        float alpha = alpha_s[qr];
        #pragma unroll
        for (int d = 0; d < 32; d++) acc[d] *= alpha;
        #pragma unroll
        for (int c = 0; c < BKT; c++) {
            float p = Ss[qr][c];
            const float4* vrow = reinterpret_cast<const float4*>(&Vs[c][dh]);
            #pragma unroll
            for (int d4 = 0; d4 < 8; d4++) {
                float4 vv = vrow[d4];
                acc[d4 * 4 + 0] += p * vv.x;
                acc[d4 * 4 + 1] += p * vv.y;
                acc[d4 * 4 + 2] += p * vv.z;
                acc[d4 * 4 + 3] += p * vv.w;
            }
        }
        __syncthreads();
    }

    float inv_l = 1.0f / l_s[qr];
    size_t orow = (size_t)(b * NN + qt * 64 + qr);
    float* op = out + orow * CC + h * HD + dh;
    #pragma unroll
    for (int d4 = 0; d4 < 8; d4++) {
        float4 r;
        r.x = acc[d4 * 4 + 0] * inv_l;
        r.y = acc[d4 * 4 + 1] * inv_l;
        r.z = acc[d4 * 4 + 2] * inv_l;
        r.w = acc[d4 * 4 + 3] * inv_l;
        *reinterpret_cast<float4*>(op + d4 * 4) = r;
    }
}

// ---------------------------------------------------------------------------
extern "C" void kernel_launch(void* const* d_in, const int* in_sizes, int n_in,
                              void* d_out, int out_size) {
    const float* x      = (const float*)d_in[0];
    const float* ln1_g  = (const float*)d_in[1];
    const float* ln1_b  = (const float*)d_in[2];
    const float* w_qk   = (const float*)d_in[3];
    const float* w_v    = (const float*)d_in[4];
    const float* ln2_g  = (const float*)d_in[5];
    const float* ln2_b  = (const float*)d_in[6];
    const float* w_proj = (const float*)d_in[7];
    const float* b_proj = (const float*)d_in[8];
    float* out = (float*)d_out;

    float *xn, *qkb, *vb, *ao, *l2;
    cudaGetSymbolAddress((void**)&xn,  g_xn);
    cudaGetSymbolAddress((void**)&qkb, g_qk);
    cudaGetSymbolAddress((void**)&vb,  g_v);
    cudaGetSymbolAddress((void**)&ao,  g_ao);
    cudaGetSymbolAddress((void**)&l2,  g_l2);

    // 1. LN1
    ln_kernel<<<MM, 256>>>(x, ln1_g, ln1_b, xn);

    // 2. projections: qk = xn @ w_qk [4096,2048], v = xn @ w_v [4096,1024]
    gemm_kernel<false><<<dim3(2 * CC / 64, MM / 64), 256>>>(xn, w_qk, nullptr, qkb, MM, 2 * CC, CC);
    gemm_kernel<false><<<dim3(CC / 64, MM / 64), 256>>>(xn, w_v, nullptr, vb, MM, CC, CC);

    // 3. flash attention
    attn_kernel<<<dim3(NN / 64, HH, BB), 128>>>(qkb, vb, ao);

    // 4. LN2
    ln_kernel<<<MM, 256>>>(ao, ln2_g, ln2_b, l2);

    // 5. output projection + bias
    gemm_kernel<true><<<dim3(CC / 64, MM / 64), 256>>>(l2, w_proj, b_proj, out, MM, CC, CC);
}

// round 2
// speedup vs baseline: 1.8132x; 1.8132x over previous
#include <cuda_runtime.h>

// Problem constants (fixed shapes)
#define BB 2
#define NN 2048
#define CC 1024
#define HH 16
#define HD 64
#define MM (BB * NN)   // 4096 rows

typedef unsigned long long ull;

// Scratch (device globals — no allocations allowed)
__device__ float g_xn[MM * CC];        // LN1 output
__device__ float g_qk[MM * 2 * CC];    // qk projection
__device__ float g_v[MM * CC];         // v projection
__device__ float g_ao[MM * CC];        // attention output
__device__ float g_l2[MM * CC];        // LN2 output

// ---------------------------------------------------------------------------
// f32x2 packed helpers (Blackwell FFMA2 path — only reachable via PTX)
// ---------------------------------------------------------------------------
__device__ __forceinline__ ull pack_dup(float x) {
    unsigned u = __float_as_uint(x);
    ull r;
    asm("mov.b64 %0, {%1, %2};" : "=l"(r) : "r"(u), "r"(u));
    return r;
}
__device__ __forceinline__ void ffma2(ull& acc, ull a, ull b) {
    asm("fma.rn.f32x2 %0, %1, %2, %0;" : "+l"(acc) : "l"(a), "l"(b));
}
__device__ __forceinline__ ull mul2(ull a, ull b) {
    ull r;
    asm("mul.rn.f32x2 %0, %1, %2;" : "=l"(r) : "l"(a), "l"(b));
    return r;
}
__device__ __forceinline__ float2 unpack2(ull v) {
    unsigned lo, hi;
    asm("mov.b64 {%0, %1}, %2;" : "=r"(lo), "=r"(hi) : "l"(v));
    return make_float2(__uint_as_float(lo), __uint_as_float(hi));
}

// ---------------------------------------------------------------------------
// LayerNorm: one block per row, 256 threads, C=1024 -> one float4 per thread
// ---------------------------------------------------------------------------
__global__ void ln_kernel(const float* __restrict__ x,
                          const float* __restrict__ g,
                          const float* __restrict__ b,
                          float* __restrict__ out) {
    int row = blockIdx.x;
    int t = threadIdx.x;  // 256
    const float4* xr = reinterpret_cast<const float4*>(x + (size_t)row * CC);
    float4 v = xr[t];
    float s  = v.x + v.y + v.z + v.w;
    float ss = v.x * v.x + v.y * v.y + v.z * v.z + v.w * v.w;

    #pragma unroll
    for (int o = 16; o > 0; o >>= 1) {
        s  += __shfl_down_sync(0xFFFFFFFFu, s,  o);
        ss += __shfl_down_sync(0xFFFFFFFFu, ss, o);
    }
    __shared__ float sh[8][2];
    int w = t >> 5, l = t & 31;
    if (l == 0) { sh[w][0] = s; sh[w][1] = ss; }
    __syncthreads();
    if (w == 0) {
        s  = (l < 8) ? sh[l][0] : 0.0f;
        ss = (l < 8) ? sh[l][1] : 0.0f;
        #pragma unroll
        for (int o = 4; o > 0; o >>= 1) {
            s  += __shfl_down_sync(0xFFFFFFFFu, s,  o);
            ss += __shfl_down_sync(0xFFFFFFFFu, ss, o);
        }
        if (l == 0) { sh[0][0] = s; sh[0][1] = ss; }
    }
    __syncthreads();
    s = sh[0][0]; ss = sh[0][1];

    float mu  = s * (1.0f / CC);
    float var = ss * (1.0f / CC) - mu * mu;
    float inv = rsqrtf(var + 1e-5f);

    const float4 gv = reinterpret_cast<const float4*>(g)[t];
    const float4 bv = reinterpret_cast<const float4*>(b)[t];
    float4 o;
    o.x = (v.x - mu) * inv * gv.x + bv.x;
    o.y = (v.y - mu) * inv * gv.y + bv.y;
    o.z = (v.z - mu) * inv * gv.z + bv.z;
    o.w = (v.w - mu) * inv * gv.w + bv.w;
    reinterpret_cast<float4*>(out + (size_t)row * CC)[t] = o;
}

// ---------------------------------------------------------------------------
// SGEMM with FFMA2: C[M,N] = A[M,K] @ B[K,N] (+bias). 128x128x16 tile,
// 256 threads, 8 m-rows x 4 n-pairs per thread (8x8 logical microtile).
// Thread (tx,ty): m = ty*8+i, n-pair j covers cols 2*tx + 32*j (+1).
// ---------------------------------------------------------------------------
template <bool BIAS>
__global__ void gemm_kernel(const float* __restrict__ A,
                            const float* __restrict__ B,
                            const float* __restrict__ bias,
                            float* __restrict__ C,
                            int M, int N, int K) {
    __shared__ float As[16][132];   // [k][m], padded
    __shared__ float Bs[16][128];   // [k][n]

    int bx = blockIdx.x;            // N tile
    int by = blockIdx.y;            // M tile
    int t = threadIdx.x;            // 256
    int tx = t & 15, ty = t >> 4;

    ull acc[8][4];
    #pragma unroll
    for (int i = 0; i < 8; i++)
        #pragma unroll
        for (int j = 0; j < 4; j++) acc[i][j] = 0ull;

    for (int k0 = 0; k0 < K; k0 += 16) {
        // load A tile 128x16 (transpose into As[k][m])
        #pragma unroll
        for (int p = 0; p < 2; p++) {
            int idx = t + p * 256;
            int row = idx >> 2;
            int c4 = (idx & 3) * 4;
            float4 a = *reinterpret_cast<const float4*>(
                A + (size_t)(by * 128 + row) * K + k0 + c4);
            As[c4 + 0][row] = a.x;
            As[c4 + 1][row] = a.y;
            As[c4 + 2][row] = a.z;
            As[c4 + 3][row] = a.w;
        }
        // load B tile 16x128
        #pragma unroll
        for (int p = 0; p < 2; p++) {
            int idx = t + p * 256;
            int krow = idx >> 5;
            int c4 = (idx & 31) * 4;
            *reinterpret_cast<float4*>(&Bs[krow][c4]) =
                *reinterpret_cast<const float4*>(
                    B + (size_t)(k0 + krow) * N + bx * 128 + c4);
        }
        __syncthreads();

        #pragma unroll
        for (int kk = 0; kk < 16; kk++) {
            float4 a0 = *reinterpret_cast<const float4*>(&As[kk][ty * 8]);
            float4 a1 = *reinterpret_cast<const float4*>(&As[kk][ty * 8 + 4]);
            ull a2[8];
            a2[0] = pack_dup(a0.x); a2[1] = pack_dup(a0.y);
            a2[2] = pack_dup(a0.z); a2[3] = pack_dup(a0.w);
            a2[4] = pack_dup(a1.x); a2[5] = pack_dup(a1.y);
            a2[6] = pack_dup(a1.z); a2[7] = pack_dup(a1.w);
            ull b2[4];
            #pragma unroll
            for (int j = 0; j < 4; j++)
                b2[j] = *reinterpret_cast<const ull*>(&Bs[kk][2 * tx + 32 * j]);
            #pragma unroll
            for (int i = 0; i < 8; i++)
                #pragma unroll
                for (int j = 0; j < 4; j++)
                    ffma2(acc[i][j], a2[i], b2[j]);
        }
        __syncthreads();
    }

    // epilogue
    #pragma unroll
    for (int i = 0; i < 8; i++) {
        int row = by * 128 + ty * 8 + i;
        #pragma unroll
        for (int j = 0; j < 4; j++) {
            int col = bx * 128 + 2 * tx + 32 * j;
            float2 r = unpack2(acc[i][j]);
            if (BIAS) {
                r.x += bias[col];
                r.y += bias[col + 1];
            }
            *reinterpret_cast<float2*>(C + (size_t)row * N + col) = r;
        }
    }
}

// ---------------------------------------------------------------------------
// fp32 flash attention with FFMA2 register tiling.
// BQ=64 queries, BK=64 keys per iter, 128 threads.
// Thread (tx,ty): q rows ty*8+i (i=0..7); k/d pair j covers 2*tx+32*j (+1).
// ---------------------------------------------------------------------------
__global__ void attn_kernel(const float* __restrict__ qk,
                            const float* __restrict__ vb,
                            float* __restrict__ out) {
    const int BQ = 64, BK = 64;
    __shared__ float Qs[BQ][68];      // [q][d] padded
    __shared__ float Kt[HD][66];      // transposed [d][k] padded
    __shared__ float Vs[BK][HD];      // [k][d]
    __shared__ float Ss[BQ][66];      // [q][k] padded (even pad for ull access)
    __shared__ float m_s[BQ], l_s[BQ], alpha_s[BQ];

    int qt = blockIdx.x, h = blockIdx.y, b = blockIdx.z;
    int t = threadIdx.x;              // 128
    int tx = t & 15, ty = t >> 4;     // ty 0..7
    const float scale = 0.125f;       // 64^-0.5

    ull o2[8][2];
    #pragma unroll
    for (int i = 0; i < 8; i++) { o2[i][0] = 0ull; o2[i][1] = 0ull; }

    // load Q tile 64x64
    for (int i = t; i < BQ * 16; i += 128) {
        int r = i >> 4, c4 = (i & 15) * 4;
        *reinterpret_cast<float4*>(&Qs[r][c4]) =
            *reinterpret_cast<const float4*>(
                qk + (size_t)(b * NN + qt * 64 + r) * (2 * CC) + h * HD + c4);
    }
    if (t < BQ) { m_s[t] = -1e30f; l_s[t] = 0.0f; }
    __syncthreads();

    for (int k0 = 0; k0 < NN; k0 += BK) {
        // load K (transposed into Kt[d][k]) and V tiles
        for (int i = t; i < BK * 16; i += 128) {
            int r = i >> 4, c4 = (i & 15) * 4;
            size_t grow = (size_t)(b * NN + k0 + r);
            float4 kv = *reinterpret_cast<const float4*>(
                qk + grow * (2 * CC) + CC + h * HD + c4);
            Kt[c4 + 0][r] = kv.x;
            Kt[c4 + 1][r] = kv.y;
            Kt[c4 + 2][r] = kv.z;
            Kt[c4 + 3][r] = kv.w;
            *reinterpret_cast<float4*>(&Vs[r][c4]) =
                *reinterpret_cast<const float4*>(vb + grow * CC + h * HD + c4);
        }
        __syncthreads();

        // S = Q @ K^T (outer product over d)
        {
            ull s2[8][2];
            #pragma unroll
            for (int i = 0; i < 8; i++) { s2[i][0] = 0ull; s2[i][1] = 0ull; }
            #pragma unroll 4
            for (int d = 0; d < HD; d++) {
                ull q2[8];
                #pragma unroll
                for (int i = 0; i < 8; i++) q2[i] = pack_dup(Qs[ty * 8 + i][d]);
                ull k2[2];
                k2[0] = *reinterpret_cast<const ull*>(&Kt[d][2 * tx]);
                k2[1] = *reinterpret_cast<const ull*>(&Kt[d][2 * tx + 32]);
                #pragma unroll
                for (int i = 0; i < 8; i++) {
                    ffma2(s2[i][0], q2[i], k2[0]);
                    ffma2(s2[i][1], q2[i], k2[1]);
                }
            }
            ull sc2 = pack_dup(scale);
            #pragma unroll
            for (int i = 0; i < 8; i++) {
                #pragma unroll
                for (int j = 0; j < 2; j++) {
                    ull v = mul2(s2[i][j], sc2);
                    *reinterpret_cast<ull*>(&Ss[ty * 8 + i][2 * tx + 32 * j]) = v;
                }
            }
        }
        __syncthreads();

        // online softmax: 2 threads per row
        {
            int row = t >> 1;
            int c0 = (t & 1) * 32;
            float m_old = m_s[row];
            float mx = -1e30f;
            #pragma unroll
            for (int c = 0; c < 32; c++) mx = fmaxf(mx, Ss[row][c0 + c]);
            mx = fmaxf(mx, __shfl_xor_sync(0xFFFFFFFFu, mx, 1));
            mx = fmaxf(mx, m_old);
            float sum = 0.0f;
            #pragma unroll
            for (int c = 0; c < 32; c++) {
                float p = __expf(Ss[row][c0 + c] - mx);
                Ss[row][c0 + c] = p;
                sum += p;
            }
            sum += __shfl_xor_sync(0xFFFFFFFFu, sum, 1);
            if ((t & 1) == 0) {
                float alpha = __expf(m_old - mx);
                m_s[row] = mx;
                l_s[row] = l_s[row] * alpha + sum;
                alpha_s[row] = alpha;
            }
        }
        __syncthreads();

        // rescale accumulators, then O += P @ V
        #pragma unroll
        for (int i = 0; i < 8; i++) {
            ull a2 = pack_dup(alpha_s[ty * 8 + i]);
            o2[i][0] = mul2(o2[i][0], a2);
            o2[i][1] = mul2(o2[i][1], a2);
        }
        #pragma unroll 4
        for (int kk = 0; kk < BK; kk++) {
            ull p2[8];
            #pragma unroll
            for (int i = 0; i < 8; i++) p2[i] = pack_dup(Ss[ty * 8 + i][kk]);
            ull v2[2];
            v2[0] = *reinterpret_cast<const ull*>(&Vs[kk][2 * tx]);
            v2[1] = *reinterpret_cast<const ull*>(&Vs[kk][2 * tx + 32]);
            #pragma unroll
            for (int i = 0; i < 8; i++) {
                ffma2(o2[i][0], p2[i], v2[0]);
                ffma2(o2[i][1], p2[i], v2[1]);
            }
        }
        __syncthreads();
    }

    // epilogue: normalize and store
    #pragma unroll
    for (int i = 0; i < 8; i++) {
        int q = ty * 8 + i;
        float inv_l = 1.0f / l_s[q];
        size_t orow = (size_t)(b * NN + qt * 64 + q);
        #pragma unroll
        for (int j = 0; j < 2; j++) {
            float2 r = unpack2(o2[i][j]);
            r.x *= inv_l;
            r.y *= inv_l;
            *reinterpret_cast<float2*>(
                out + orow * CC + h * HD + 2 * tx + 32 * j) = r;
        }
    }
}

// ---------------------------------------------------------------------------
extern "C" void kernel_launch(void* const* d_in, const int* in_sizes, int n_in,
                              void* d_out, int out_size) {
    const float* x      = (const float*)d_in[0];
    const float* ln1_g  = (const float*)d_in[1];
    const float* ln1_b  = (const float*)d_in[2];
    const float* w_qk   = (const float*)d_in[3];
    const float* w_v    = (const float*)d_in[4];
    const float* ln2_g  = (const float*)d_in[5];
    const float* ln2_b  = (const float*)d_in[6];
    const float* w_proj = (const float*)d_in[7];
    const float* b_proj = (const float*)d_in[8];
    float* out = (float*)d_out;

    float *xn, *qkb, *vb, *ao, *l2;
    cudaGetSymbolAddress((void**)&xn,  g_xn);
    cudaGetSymbolAddress((void**)&qkb, g_qk);
    cudaGetSymbolAddress((void**)&vb,  g_v);
    cudaGetSymbolAddress((void**)&ao,  g_ao);
    cudaGetSymbolAddress((void**)&l2,  g_l2);

    // 1. LN1
    ln_kernel<<<MM, 256>>>(x, ln1_g, ln1_b, xn);

    // 2. projections
    gemm_kernel<false><<<dim3(2 * CC / 128, MM / 128), 256>>>(xn, w_qk, nullptr, qkb, MM, 2 * CC, CC);
    gemm_kernel<false><<<dim3(CC / 128, MM / 128), 256>>>(xn, w_v, nullptr, vb, MM, CC, CC);

    // 3. flash attention
    attn_kernel<<<dim3(NN / 64, HH, BB), 128>>>(qkb, vb, ao);

    // 4. LN2
    ln_kernel<<<MM, 256>>>(ao, ln2_g, ln2_b, l2);

    // 5. output projection + bias
    gemm_kernel<true><<<dim3(CC / 128, MM / 128), 256>>>(l2, w_proj, b_proj, out, MM, CC, CC);
}

// round 4
// speedup vs baseline: 2.3716x; 1.3080x over previous
#include <cuda_runtime.h>
#include <cuda_bf16.h>
#include <cstdint>

// Problem constants (fixed shapes)
#define BB 2
#define NN 2048
#define CC 1024
#define HH 16
#define HD 64
#define MM (BB * NN)   // 4096 rows

typedef unsigned long long ull;
typedef __nv_bfloat16 bf16;

// ---------------------------------------------------------------------------
// Scratch (device globals — no allocations allowed)
// ---------------------------------------------------------------------------
__device__ float g_xn[MM * CC];
__device__ float g_qk[MM * 2 * CC];
__device__ float g_v[MM * CC];
__device__ float g_ao[MM * CC];
__device__ float g_l2[MM * CC];
__device__ bf16 g_xh[MM * CC], g_xl[MM * CC];
__device__ bf16 g_wqkT_h[2 * CC * CC], g_wqkT_l[2 * CC * CC];
__device__ bf16 g_wvT_h[CC * CC], g_wvT_l[CC * CC];
__device__ bf16 g_wpT_h[CC * CC], g_wpT_l[CC * CC];

// ---------------------------------------------------------------------------
// helpers
// ---------------------------------------------------------------------------
__device__ __forceinline__ uint32_t smem_u32(const void* p) {
    uint32_t a;
    asm("{ .reg .u64 t; cvta.to.shared.u64 t, %1; cvt.u32.u64 %0, t; }"
        : "=r"(a) : "l"(p));
    return a;
}

__device__ __forceinline__ void mma_bf16(float* c, const unsigned* a, const unsigned* b) {
    asm volatile(
        "mma.sync.aligned.m16n8k16.row.col.f32.bf16.bf16.f32 "
        "{%0,%1,%2,%3}, {%4,%5,%6,%7}, {%8,%9}, {%0,%1,%2,%3};"
        : "+f"(c[0]), "+f"(c[1]), "+f"(c[2]), "+f"(c[3])
        : "r"(a[0]), "r"(a[1]), "r"(a[2]), "r"(a[3]), "r"(b[0]), "r"(b[1]));
}

__device__ __forceinline__ void ldm_x4(unsigned* r, uint32_t addr) {
    asm volatile("ldmatrix.sync.aligned.m8n8.x4.shared.b16 {%0,%1,%2,%3}, [%4];"
        : "=r"(r[0]), "=r"(r[1]), "=r"(r[2]), "=r"(r[3]) : "r"(addr));
}

// f32x2 packed helpers (FFMA2 path, used by attention)
__device__ __forceinline__ ull pack_dup(float x) {
    unsigned u = __float_as_uint(x);
    ull r;
    asm("mov.b64 %0, {%1, %2};" : "=l"(r) : "r"(u), "r"(u));
    return r;
}
__device__ __forceinline__ void ffma2(ull& acc, ull a, ull b) {
    asm("fma.rn.f32x2 %0, %1, %2, %0;" : "+l"(acc) : "l"(a), "l"(b));
}
__device__ __forceinline__ ull mul2(ull a, ull b) {
    ull r;
    asm("mul.rn.f32x2 %0, %1, %2;" : "=l"(r) : "l"(a), "l"(b));
    return r;
}
__device__ __forceinline__ float2 unpack2(ull v) {
    unsigned lo, hi;
    asm("mov.b64 {%0, %1}, %2;" : "=r"(lo), "=r"(hi) : "l"(v));
    return make_float2(__uint_as_float(lo), __uint_as_float(hi));
}

// ---------------------------------------------------------------------------
// LayerNorm
// ---------------------------------------------------------------------------
__global__ void ln_kernel(const float* __restrict__ x,
                          const float* __restrict__ g,
                          const float* __restrict__ b,
                          float* __restrict__ out) {
    int row = blockIdx.x;
    int t = threadIdx.x;
    const float4* xr = reinterpret_cast<const float4*>(x + (size_t)row * CC);
    float4 v = xr[t];
    float s  = v.x + v.y + v.z + v.w;
    float ss = v.x * v.x + v.y * v.y + v.z * v.z + v.w * v.w;

    #pragma unroll
    for (int o = 16; o > 0; o >>= 1) {
        s  += __shfl_down_sync(0xFFFFFFFFu, s,  o);
        ss += __shfl_down_sync(0xFFFFFFFFu, ss, o);
    }
    __shared__ float sh[8][2];
    int w = t >> 5, l = t & 31;
    if (l == 0) { sh[w][0] = s; sh[w][1] = ss; }
    __syncthreads();
    if (w == 0) {
        s  = (l < 8) ? sh[l][0] : 0.0f;
        ss = (l < 8) ? sh[l][1] : 0.0f;
        #pragma unroll
        for (int o = 4; o > 0; o >>= 1) {
            s  += __shfl_down_sync(0xFFFFFFFFu, s,  o);
            ss += __shfl_down_sync(0xFFFFFFFFu, ss, o);
        }
        if (l == 0) { sh[0][0] = s; sh[0][1] = ss; }
    }
    __syncthreads();
    s = sh[0][0]; ss = sh[0][1];

    float mu  = s * (1.0f / CC);
    float var = ss * (1.0f / CC) - mu * mu;
    float inv = rsqrtf(var + 1e-5f);

    const float4 gv = reinterpret_cast<const float4*>(g)[t];
    const float4 bv = reinterpret_cast<const float4*>(b)[t];
    float4 o;
    o.x = (v.x - mu) * inv * gv.x + bv.x;
    o.y = (v.y - mu) * inv * gv.y + bv.y;
    o.z = (v.z - mu) * inv * gv.z + bv.z;
    o.w = (v.w - mu) * inv * gv.w + bv.w;
    reinterpret_cast<float4*>(out + (size_t)row * CC)[t] = o;
}

// ---------------------------------------------------------------------------
// Split fp32 -> bf16 hi + bf16 lo (same layout)
// ---------------------------------------------------------------------------
__global__ void split_kernel(const float* __restrict__ x,
                             bf16* __restrict__ h,
                             bf16* __restrict__ l) {
    int i = blockIdx.x * 256 + threadIdx.x;
    float4 v = reinterpret_cast<const float4*>(x)[i];
    bf16 h0 = __float2bfloat16(v.x), h1 = __float2bfloat16(v.y);
    bf16 h2 = __float2bfloat16(v.z), h3 = __float2bfloat16(v.w);
    bf16 l0 = __float2bfloat16(v.x - __bfloat162float(h0));
    bf16 l1 = __float2bfloat16(v.y - __bfloat162float(h1));
    bf16 l2 = __float2bfloat16(v.z - __bfloat162float(h2));
    bf16 l3 = __float2bfloat16(v.w - __bfloat162float(h3));
    __nv_bfloat162* hp = reinterpret_cast<__nv_bfloat162*>(h + (size_t)i * 4);
    __nv_bfloat162* lp = reinterpret_cast<__nv_bfloat162*>(l + (size_t)i * 4);
    hp[0] = __halves2bfloat162(h0, h1);
    hp[1] = __halves2bfloat162(h2, h3);
    lp[0] = __halves2bfloat162(l0, l1);
    lp[1] = __halves2bfloat162(l2, l3);
}

// ---------------------------------------------------------------------------
// Transpose + split: w[K][N] fp32 -> wT_hi/lo[N][K] bf16
// ---------------------------------------------------------------------------
__global__ void wsplit_kernel(const float* __restrict__ w,
                              bf16* __restrict__ th,
                              bf16* __restrict__ tl,
                              int K, int N) {
    __shared__ float t[32][33];
    int bx = blockIdx.x, by = blockIdx.y;
    int x = bx * 32 + threadIdx.x;
    #pragma unroll
    for (int j = 0; j < 32; j += 8)
        t[threadIdx.y + j][threadIdx.x] = w[(size_t)(by * 32 + threadIdx.y + j) * N + x];
    __syncthreads();
    int n = bx * 32 + threadIdx.y;
    int k = by * 32 + threadIdx.x;
    #pragma unroll
    for (int j = 0; j < 32; j += 8) {
        float v = t[threadIdx.x][threadIdx.y + j];
        bf16 h = __float2bfloat16(v);
        th[(size_t)(n + j) * K + k] = h;
        tl[(size_t)(n + j) * K + k] = __float2bfloat16(v - __bfloat162float(h));
    }
}

// ---------------------------------------------------------------------------
// mma.sync bf16x3 GEMM: C[M,N] = A @ B^T (+bias), fp32-equivalent precision.
// Ah/Al [M,K] bf16, Bh/Bl [N,K] bf16 (pre-transposed). CTA = 128x128 tile,
// 256 threads = 8 warps (2x4), warp tile 64x32 (4x4 m16n8k16 frags).
// K chunked by 16, double-buffered smem, rows padded to 24 bf16 (48B:
// 8 consecutive rows hit 8 distinct 16B banks -> ldmatrix conflict-free).
// ---------------------------------------------------------------------------
#define KC 16
#define PAD 24

template <bool BIAS>
__global__ void __launch_bounds__(256)
gemm_mma(const bf16* __restrict__ Ah, const bf16* __restrict__ Al,
         const bf16* __restrict__ Bh, const bf16* __restrict__ Bl,
         const float* __restrict__ bias, float* __restrict__ C,
         int M, int N, int K) {
    __shared__ bf16 sAh[2][128 * PAD];
    __shared__ bf16 sAl[2][128 * PAD];
    __shared__ bf16 sBh[2][128 * PAD];
    __shared__ bf16 sBl[2][128 * PAD];

    int tid = threadIdx.x;
    int warp = tid >> 5, lane = tid & 31;
    int wm = warp >> 2, wn = warp & 3;          // 2 x 4 warp grid
    int m0 = blockIdx.y * 128, n0 = blockIdx.x * 128;

    // gmem load mapping: 1 uint4 (8 bf16) per thread per tensor
    int lr = tid >> 1;                           // row 0..127
    int lk = (tid & 1) * 8;                      // k offset 0/8
    const bf16* gAh = Ah + (size_t)(m0 + lr) * K + lk;
    const bf16* gAl = Al + (size_t)(m0 + lr) * K + lk;
    const bf16* gBh = Bh + (size_t)(n0 + lr) * K + lk;
    const bf16* gBl = Bl + (size_t)(n0 + lr) * K + lk;
    int so = lr * PAD + lk;                      // smem element offset

    float acc[4][4][4];
    #pragma unroll
    for (int i = 0; i < 4; i++)
        #pragma unroll
        for (int j = 0; j < 4; j++)
            #pragma unroll
            for (int q = 0; q < 4; q++) acc[i][j][q] = 0.0f;

    // ldmatrix lane address components
    //   A frags (x4): row = mt*16 + (lane&15), colByte = ((lane>>4)&1)*16
    //   B frags (x4): row = np*16 + ((lane>>4)&1)*8 + (lane&7), colByte = ((lane>>3)&1)*16
    int a_row = wm * 64 + (lane & 15);
    int a_cb  = ((lane >> 4) & 1) * 16;
    int b_row = wn * 32 + ((lane >> 4) & 1) * 8 + (lane & 7);
    int b_cb  = ((lane >> 3) & 1) * 16;

    // prologue: chunk 0
    uint4 ra = *reinterpret_cast<const uint4*>(gAh);
    uint4 rb = *reinterpret_cast<const uint4*>(gAl);
    uint4 rc = *reinterpret_cast<const uint4*>(gBh);
    uint4 rd = *reinterpret_cast<const uint4*>(gBl);
    *reinterpret_cast<uint4*>(&sAh[0][so]) = ra;
    *reinterpret_cast<uint4*>(&sAl[0][so]) = rb;
    *reinterpret_cast<uint4*>(&sBh[0][so]) = rc;
    *reinterpret_cast<uint4*>(&sBl[0][so]) = rd;
    __syncthreads();

    int nch = K / KC;
    #pragma unroll 1
    for (int c = 0; c < nch; c++) {
        int cur = c & 1;
        if (c + 1 < nch) {
            ra = *reinterpret_cast<const uint4*>(gAh + (c + 1) * KC);
            rb = *reinterpret_cast<const uint4*>(gAl + (c + 1) * KC);
            rc = *reinterpret_cast<const uint4*>(gBh + (c + 1) * KC);
            rd = *reinterpret_cast<const uint4*>(gBl + (c + 1) * KC);
        }

        uint32_t baseAh = smem_u32(&sAh[cur][0]);
        uint32_t baseAl = smem_u32(&sAl[cur][0]);
        uint32_t baseBh = smem_u32(&sBh[cur][0]);
        uint32_t baseBl = smem_u32(&sBl[cur][0]);

        unsigned fA[4][4], fBh[4][2], fBl[4][2];
        // B hi/lo frags: 2 x ldmatrix.x4 each (covers 2 n-tiles per call)
        #pragma unroll
        for (int np = 0; np < 2; np++) {
            unsigned r4[4];
            uint32_t ab = baseBh + (uint32_t)(b_row + np * 16) * (PAD * 2) + b_cb;
            ldm_x4(r4, ab);
            fBh[np * 2 + 0][0] = r4[0]; fBh[np * 2 + 0][1] = r4[1];
            fBh[np * 2 + 1][0] = r4[2]; fBh[np * 2 + 1][1] = r4[3];
            ab = baseBl + (uint32_t)(b_row + np * 16) * (PAD * 2) + b_cb;
            ldm_x4(r4, ab);
            fBl[np * 2 + 0][0] = r4[0]; fBl[np * 2 + 0][1] = r4[1];
            fBl[np * 2 + 1][0] = r4[2]; fBl[np * 2 + 1][1] = r4[3];
        }
        // A hi frags
        #pragma unroll
        for (int mt = 0; mt < 4; mt++)
            ldm_x4(fA[mt], baseAh + (uint32_t)(a_row + mt * 16) * (PAD * 2) + a_cb);
        // pass 1: Ah x Bh ; pass 2: Ah x Bl
        #pragma unroll
        for (int mt = 0; mt < 4; mt++)
            #pragma unroll
            for (int nt = 0; nt < 4; nt++)
                mma_bf16(acc[mt][nt], fA[mt], fBh[nt]);
        #pragma unroll
        for (int mt = 0; mt < 4; mt++)
            #pragma unroll
            for (int nt = 0; nt < 4; nt++)
                mma_bf16(acc[mt][nt], fA[mt], fBl[nt]);
        // A lo frags (reuse regs), pass 3: Al x Bh
        #pragma unroll
        for (int mt = 0; mt < 4; mt++)
            ldm_x4(fA[mt], baseAl + (uint32_t)(a_row + mt * 16) * (PAD * 2) + a_cb);
        #pragma unroll
        for (int mt = 0; mt < 4; mt++)
            #pragma unroll
            for (int nt = 0; nt < 4; nt++)
                mma_bf16(acc[mt][nt], fA[mt], fBh[nt]);

        if (c + 1 < nch) {
            int nxt = cur ^ 1;
            *reinterpret_cast<uint4*>(&sAh[nxt][so]) = ra;
            *reinterpret_cast<uint4*>(&sAl[nxt][so]) = rb;
            *reinterpret_cast<uint4*>(&sBh[nxt][so]) = rc;
            *reinterpret_cast<uint4*>(&sBl[nxt][so]) = rd;
        }
        __syncthreads();
    }

    // epilogue: direct fp32 stores (+bias)
    #pragma unroll
    for (int mt = 0; mt < 4; mt++) {
        int row = m0 + wm * 64 + mt * 16 + (lane >> 2);
        #pragma unroll
        for (int nt = 0; nt < 4; nt++) {
            int col = n0 + wn * 32 + nt * 8 + (lane & 3) * 2;
            float bx = 0.f, by = 0.f;
            if (BIAS) { bx = bias[col]; by = bias[col + 1]; }
            float2 r0 = make_float2(acc[mt][nt][0] + bx, acc[mt][nt][1] + by);
            float2 r1 = make_float2(acc[mt][nt][2] + bx, acc[mt][nt][3] + by);
            *reinterpret_cast<float2*>(C + (size_t)row * N + col) = r0;
            *reinterpret_cast<float2*>(C + (size_t)(row + 8) * N + col) = r1;
        }
    }
}

// ---------------------------------------------------------------------------
// fp32 flash attention with FFMA2 register tiling (unchanged, measured 891us)
// ---------------------------------------------------------------------------
__global__ void attn_kernel(const float* __restrict__ qk,
                            const float* __restrict__ vb,
                            float* __restrict__ out) {
    const int BQ = 64, BK = 64;
    __shared__ float Qs[BQ][68];
    __shared__ float Kt[HD][66];
    __shared__ float Vs[BK][HD];
    __shared__ float Ss[BQ][66];
    __shared__ float m_s[BQ], l_s[BQ], alpha_s[BQ];

    int qt = blockIdx.x, h = blockIdx.y, b = blockIdx.z;
    int t = threadIdx.x;
    int tx = t & 15, ty = t >> 4;
    const float scale = 0.125f;

    ull o2[8][2];
    #pragma unroll
    for (int i = 0; i < 8; i++) { o2[i][0] = 0ull; o2[i][1] = 0ull; }

    for (int i = t; i < BQ * 16; i += 128) {
        int r = i >> 4, c4 = (i & 15) * 4;
        *reinterpret_cast<float4*>(&Qs[r][c4]) =
            *reinterpret_cast<const float4*>(
                qk + (size_t)(b * NN + qt * 64 + r) * (2 * CC) + h * HD + c4);
    }
    if (t < BQ) { m_s[t] = -1e30f; l_s[t] = 0.0f; }
    __syncthreads();

    for (int k0 = 0; k0 < NN; k0 += BK) {
        for (int i = t; i < BK * 16; i += 128) {
            int r = i >> 4, c4 = (i & 15) * 4;
            size_t grow = (size_t)(b * NN + k0 + r);
            float4 kv = *reinterpret_cast<const float4*>(
                qk + grow * (2 * CC) + CC + h * HD + c4);
            Kt[c4 + 0][r] = kv.x;
            Kt[c4 + 1][r] = kv.y;
            Kt[c4 + 2][r] = kv.z;
            Kt[c4 + 3][r] = kv.w;
            *reinterpret_cast<float4*>(&Vs[r][c4]) =
                *reinterpret_cast<const float4*>(vb + grow * CC + h * HD + c4);
        }
        __syncthreads();

        {
            ull s2[8][2];
            #pragma unroll
            for (int i = 0; i < 8; i++) { s2[i][0] = 0ull; s2[i][1] = 0ull; }
            #pragma unroll 4
            for (int d = 0; d < HD; d++) {
                ull q2[8];
                #pragma unroll
                for (int i = 0; i < 8; i++) q2[i] = pack_dup(Qs[ty * 8 + i][d]);
                ull k2[2];
                k2[0] = *reinterpret_cast<const ull*>(&Kt[d][2 * tx]);
                k2[1] = *reinterpret_cast<const ull*>(&Kt[d][2 * tx + 32]);
                #pragma unroll
                for (int i = 0; i < 8; i++) {
                    ffma2(s2[i][0], q2[i], k2[0]);
                    ffma2(s2[i][1], q2[i], k2[1]);
                }
            }
            ull sc2 = pack_dup(scale);
            #pragma unroll
            for (int i = 0; i < 8; i++) {
                #pragma unroll
                for (int j = 0; j < 2; j++) {
                    ull v = mul2(s2[i][j], sc2);
                    *reinterpret_cast<ull*>(&Ss[ty * 8 + i][2 * tx + 32 * j]) = v;
                }
            }
        }
        __syncthreads();

        {
            int row = t >> 1;
            int c0 = (t & 1) * 32;
            float m_old = m_s[row];
            float mx = -1e30f;
            #pragma unroll
            for (int c = 0; c < 32; c++) mx = fmaxf(mx, Ss[row][c0 + c]);
            mx = fmaxf(mx, __shfl_xor_sync(0xFFFFFFFFu, mx, 1));
            mx = fmaxf(mx, m_old);
            float sum = 0.0f;
            #pragma unroll
            for (int c = 0; c < 32; c++) {
                float p = __expf(Ss[row][c0 + c] - mx);
                Ss[row][c0 + c] = p;
                sum += p;
            }
            sum += __shfl_xor_sync(0xFFFFFFFFu, sum, 1);
            if ((t & 1) == 0) {
                float alpha = __expf(m_old - mx);
                m_s[row] = mx;
                l_s[row] = l_s[row] * alpha + sum;
                alpha_s[row] = alpha;
            }
        }
        __syncthreads();

        #pragma unroll
        for (int i = 0; i < 8; i++) {
            ull a2 = pack_dup(alpha_s[ty * 8 + i]);
            o2[i][0] = mul2(o2[i][0], a2);
            o2[i][1] = mul2(o2[i][1], a2);
        }
        #pragma unroll 4
        for (int kk = 0; kk < BK; kk++) {
            ull p2[8];
            #pragma unroll
            for (int i = 0; i < 8; i++) p2[i] = pack_dup(Ss[ty * 8 + i][kk]);
            ull v2[2];
            v2[0] = *reinterpret_cast<const ull*>(&Vs[kk][2 * tx]);
            v2[1] = *reinterpret_cast<const ull*>(&Vs[kk][2 * tx + 32]);
            #pragma unroll
            for (int i = 0; i < 8; i++) {
                ffma2(o2[i][0], p2[i], v2[0]);
                ffma2(o2[i][1], p2[i], v2[1]);
            }
        }
        __syncthreads();
    }

    #pragma unroll
    for (int i = 0; i < 8; i++) {
        int q = ty * 8 + i;
        float inv_l = 1.0f / l_s[q];
        size_t orow = (size_t)(b * NN + qt * 64 + q);
        #pragma unroll
        for (int j = 0; j < 2; j++) {
            float2 r = unpack2(o2[i][j]);
            r.x *= inv_l;
            r.y *= inv_l;
            *reinterpret_cast<float2*>(
                out + orow * CC + h * HD + 2 * tx + 32 * j) = r;
        }
    }
}

// ---------------------------------------------------------------------------
extern "C" void kernel_launch(void* const* d_in, const int* in_sizes, int n_in,
                              void* d_out, int out_size) {
    const float* x      = (const float*)d_in[0];
    const float* ln1_g  = (const float*)d_in[1];
    const float* ln1_b  = (const float*)d_in[2];
    const float* w_qk   = (const float*)d_in[3];
    const float* w_v    = (const float*)d_in[4];
    const float* ln2_g  = (const float*)d_in[5];
    const float* ln2_b  = (const float*)d_in[6];
    const float* w_proj = (const float*)d_in[7];
    const float* b_proj = (const float*)d_in[8];
    float* out = (float*)d_out;

    float *xn, *qkb, *vb, *ao, *l2;
    bf16 *xh, *xl, *wqkh, *wqkl, *wvh, *wvl, *wph, *wpl;
    cudaGetSymbolAddress((void**)&xn,   g_xn);
    cudaGetSymbolAddress((void**)&qkb,  g_qk);
    cudaGetSymbolAddress((void**)&vb,   g_v);
    cudaGetSymbolAddress((void**)&ao,   g_ao);
    cudaGetSymbolAddress((void**)&l2,   g_l2);
    cudaGetSymbolAddress((void**)&xh,   g_xh);
    cudaGetSymbolAddress((void**)&xl,   g_xl);
    cudaGetSymbolAddress((void**)&wqkh, g_wqkT_h);
    cudaGetSymbolAddress((void**)&wqkl, g_wqkT_l);
    cudaGetSymbolAddress((void**)&wvh,  g_wvT_h);
    cudaGetSymbolAddress((void**)&wvl,  g_wvT_l);
    cudaGetSymbolAddress((void**)&wph,  g_wpT_h);
    cudaGetSymbolAddress((void**)&wpl,  g_wpT_l);

    // weight transpose+split
    wsplit_kernel<<<dim3(2 * CC / 32, CC / 32), dim3(32, 8)>>>(w_qk, wqkh, wqkl, CC, 2 * CC);
    wsplit_kernel<<<dim3(CC / 32, CC / 32), dim3(32, 8)>>>(w_v, wvh, wvl, CC, CC);
    wsplit_kernel<<<dim3(CC / 32, CC / 32), dim3(32, 8)>>>(w_proj, wph, wpl, CC, CC);

    // 1. LN1 + split
    ln_kernel<<<MM, 256>>>(x, ln1_g, ln1_b, xn);
    split_kernel<<<MM * CC / 1024, 256>>>(xn, xh, xl);

    // 2. projections on tensor cores (mma.sync bf16x3)
    gemm_mma<false><<<dim3(2 * CC / 128, MM / 128), 256>>>(
        xh, xl, wqkh, wqkl, nullptr, qkb, MM, 2 * CC, CC);
    gemm_mma<false><<<dim3(CC / 128, MM / 128), 256>>>(
        xh, xl, wvh, wvl, nullptr, vb, MM, CC, CC);

    // 3. flash attention (fp32 FFMA2)
    attn_kernel<<<dim3(NN / 64, HH, BB), 128>>>(qkb, vb, ao);

    // 4. LN2 + split
    ln_kernel<<<MM, 256>>>(ao, ln2_g, ln2_b, l2);
    split_kernel<<<MM * CC / 1024, 256>>>(l2, xh, xl);

    // 5. output projection + bias on tensor cores
    gemm_mma<true><<<dim3(CC / 128, MM / 128), 256>>>(
        xh, xl, wph, wpl, b_proj, out, MM, CC, CC);
}

// round 5
// speedup vs baseline: 4.3795x; 1.8466x over previous
#include <cuda_runtime.h>
#include <cuda_bf16.h>
#include <cstdint>

// Problem constants (fixed shapes)
#define BB 2
#define NN 2048
#define CC 1024
#define HH 16
#define HD 64
#define MM (BB * NN)   // 4096 rows

typedef __nv_bfloat16 bf16;

// ---------------------------------------------------------------------------
// Scratch (device globals — no allocations allowed)
// ---------------------------------------------------------------------------
__device__ float g_ao[MM * CC];
__device__ bf16 g_xh[MM * CC], g_xl[MM * CC];
__device__ bf16 g_qkh[MM * 2 * CC], g_qkl[MM * 2 * CC];
__device__ bf16 g_vh[MM * CC], g_vl[MM * CC];
__device__ bf16 g_wqkT_h[2 * CC * CC], g_wqkT_l[2 * CC * CC];
__device__ bf16 g_wvT_h[CC * CC], g_wvT_l[CC * CC];
__device__ bf16 g_wpT_h[CC * CC], g_wpT_l[CC * CC];

// ---------------------------------------------------------------------------
// helpers
// ---------------------------------------------------------------------------
__device__ __forceinline__ uint32_t smem_u32(const void* p) {
    uint32_t a;
    asm("{ .reg .u64 t; cvta.to.shared.u64 t, %1; cvt.u32.u64 %0, t; }"
        : "=r"(a) : "l"(p));
    return a;
}

__device__ __forceinline__ void mma_bf16(float* c, const unsigned* a, const unsigned* b) {
    asm volatile(
        "mma.sync.aligned.m16n8k16.row.col.f32.bf16.bf16.f32 "
        "{%0,%1,%2,%3}, {%4,%5,%6,%7}, {%8,%9}, {%0,%1,%2,%3};"
        : "+f"(c[0]), "+f"(c[1]), "+f"(c[2]), "+f"(c[3])
        : "r"(a[0]), "r"(a[1]), "r"(a[2]), "r"(a[3]), "r"(b[0]), "r"(b[1]));
}

__device__ __forceinline__ void ldm_x4(unsigned* r, uint32_t addr) {
    asm volatile("ldmatrix.sync.aligned.m8n8.x4.shared.b16 {%0,%1,%2,%3}, [%4];"
        : "=r"(r[0]), "=r"(r[1]), "=r"(r[2]), "=r"(r[3]) : "r"(addr));
}
__device__ __forceinline__ void ldm_x4t(unsigned* r, uint32_t addr) {
    asm volatile("ldmatrix.sync.aligned.m8n8.x4.trans.shared.b16 {%0,%1,%2,%3}, [%4];"
        : "=r"(r[0]), "=r"(r[1]), "=r"(r[2]), "=r"(r[3]) : "r"(addr));
}

// pack two f32 -> bf16x2 register (lo = first arg)
__device__ __forceinline__ unsigned pack_bf2(float lo, float hi) {
    unsigned r;
    asm("cvt.rn.bf16x2.f32 %0, %1, %2;" : "=r"(r) : "f"(hi), "f"(lo));
    return r;
}
__device__ __forceinline__ float bf_round(float x) {
    return __bfloat162float(__float2bfloat16(x));
}

// ---------------------------------------------------------------------------
// LayerNorm -> bf16 hi/lo split output
// ---------------------------------------------------------------------------
__global__ void ln_split_kernel(const float* __restrict__ x,
                                const float* __restrict__ g,
                                const float* __restrict__ b,
                                bf16* __restrict__ oh,
                                bf16* __restrict__ ol) {
    int row = blockIdx.x;
    int t = threadIdx.x;
    const float4* xr = reinterpret_cast<const float4*>(x + (size_t)row * CC);
    float4 v = xr[t];
    float s  = v.x + v.y + v.z + v.w;
    float ss = v.x * v.x + v.y * v.y + v.z * v.z + v.w * v.w;

    #pragma unroll
    for (int o = 16; o > 0; o >>= 1) {
        s  += __shfl_down_sync(0xFFFFFFFFu, s,  o);
        ss += __shfl_down_sync(0xFFFFFFFFu, ss, o);
    }
    __shared__ float sh[8][2];
    int w = t >> 5, l = t & 31;
    if (l == 0) { sh[w][0] = s; sh[w][1] = ss; }
    __syncthreads();
    if (w == 0) {
        s  = (l < 8) ? sh[l][0] : 0.0f;
        ss = (l < 8) ? sh[l][1] : 0.0f;
        #pragma unroll
        for (int o = 4; o > 0; o >>= 1) {
            s  += __shfl_down_sync(0xFFFFFFFFu, s,  o);
            ss += __shfl_down_sync(0xFFFFFFFFu, ss, o);
        }
        if (l == 0) { sh[0][0] = s; sh[0][1] = ss; }
    }
    __syncthreads();
    s = sh[0][0]; ss = sh[0][1];

    float mu  = s * (1.0f / CC);
    float var = ss * (1.0f / CC) - mu * mu;
    float inv = rsqrtf(var + 1e-5f);

    const float4 gv = reinterpret_cast<const float4*>(g)[t];
    const float4 bv = reinterpret_cast<const float4*>(b)[t];
    float o0 = (v.x - mu) * inv * gv.x + bv.x;
    float o1 = (v.y - mu) * inv * gv.y + bv.y;
    float o2 = (v.z - mu) * inv * gv.z + bv.z;
    float o3 = (v.w - mu) * inv * gv.w + bv.w;

    unsigned h01 = pack_bf2(o0, o1), h23 = pack_bf2(o2, o3);
    unsigned l01 = pack_bf2(o0 - bf_round(o0), o1 - bf_round(o1));
    unsigned l23 = pack_bf2(o2 - bf_round(o2), o3 - bf_round(o3));
    uint2* hp = reinterpret_cast<uint2*>(oh + (size_t)row * CC + t * 4);
    uint2* lp = reinterpret_cast<uint2*>(ol + (size_t)row * CC + t * 4);
    *hp = make_uint2(h01, h23);
    *lp = make_uint2(l01, l23);
}

// ---------------------------------------------------------------------------
// Transpose + split: w[K][N] fp32 -> wT_hi/lo[N][K] bf16
// ---------------------------------------------------------------------------
__global__ void wsplit_kernel(const float* __restrict__ w,
                              bf16* __restrict__ th,
                              bf16* __restrict__ tl,
                              int K, int N) {
    __shared__ float t[32][33];
    int bx = blockIdx.x, by = blockIdx.y;
    int x = bx * 32 + threadIdx.x;
    #pragma unroll
    for (int j = 0; j < 32; j += 8)
        t[threadIdx.y + j][threadIdx.x] = w[(size_t)(by * 32 + threadIdx.y + j) * N + x];
    __syncthreads();
    int n = bx * 32 + threadIdx.y;
    int k = by * 32 + threadIdx.x;
    #pragma unroll
    for (int j = 0; j < 32; j += 8) {
        float v = t[threadIdx.x][threadIdx.y + j];
        bf16 h = __float2bfloat16(v);
        th[(size_t)(n + j) * K + k] = h;
        tl[(size_t)(n + j) * K + k] = __float2bfloat16(v - __bfloat162float(h));
    }
}

// ---------------------------------------------------------------------------
// mma.sync bf16x3 GEMM. SPLIT=false: fp32 out (+bias). SPLIT=true: bf16 hi/lo
// out, with cols < qcols scaled by 0.125 (exact exponent shift for q).
// CTA 128x128 tile, 8 warps (2x4), warp 64x32, K chunk 16, double-buffered.
// ---------------------------------------------------------------------------
#define KC 16
#define PAD 24

template <bool SPLIT>
__global__ void __launch_bounds__(256)
gemm_mma(const bf16* __restrict__ Ah, const bf16* __restrict__ Al,
         const bf16* __restrict__ Bh, const bf16* __restrict__ Bl,
         const float* __restrict__ bias, float* __restrict__ C,
         bf16* __restrict__ Ch, bf16* __restrict__ Cl,
         int M, int N, int K, int qcols) {
    __shared__ bf16 sAh[2][128 * PAD];
    __shared__ bf16 sAl[2][128 * PAD];
    __shared__ bf16 sBh[2][128 * PAD];
    __shared__ bf16 sBl[2][128 * PAD];

    int tid = threadIdx.x;
    int warp = tid >> 5, lane = tid & 31;
    int wm = warp >> 2, wn = warp & 3;
    int m0 = blockIdx.y * 128, n0 = blockIdx.x * 128;

    int lr = tid >> 1;
    int lk = (tid & 1) * 8;
    const bf16* gAh = Ah + (size_t)(m0 + lr) * K + lk;
    const bf16* gAl = Al + (size_t)(m0 + lr) * K + lk;
    const bf16* gBh = Bh + (size_t)(n0 + lr) * K + lk;
    const bf16* gBl = Bl + (size_t)(n0 + lr) * K + lk;
    int so = lr * PAD + lk;

    float acc[4][4][4];
    #pragma unroll
    for (int i = 0; i < 4; i++)
        #pragma unroll
        for (int j = 0; j < 4; j++)
            #pragma unroll
            for (int q = 0; q < 4; q++) acc[i][j][q] = 0.0f;

    int a_row = wm * 64 + (lane & 15);
    int a_cb  = ((lane >> 4) & 1) * 16;
    int b_row = wn * 32 + ((lane >> 4) & 1) * 8 + (lane & 7);
    int b_cb  = ((lane >> 3) & 1) * 16;

    uint4 ra = *reinterpret_cast<const uint4*>(gAh);
    uint4 rb = *reinterpret_cast<const uint4*>(gAl);
    uint4 rc = *reinterpret_cast<const uint4*>(gBh);
    uint4 rd = *reinterpret_cast<const uint4*>(gBl);
    *reinterpret_cast<uint4*>(&sAh[0][so]) = ra;
    *reinterpret_cast<uint4*>(&sAl[0][so]) = rb;
    *reinterpret_cast<uint4*>(&sBh[0][so]) = rc;
    *reinterpret_cast<uint4*>(&sBl[0][so]) = rd;
    __syncthreads();

    int nch = K / KC;
    #pragma unroll 1
    for (int c = 0; c < nch; c++) {
        int cur = c & 1;
        if (c + 1 < nch) {
            ra = *reinterpret_cast<const uint4*>(gAh + (c + 1) * KC);
            rb = *reinterpret_cast<const uint4*>(gAl + (c + 1) * KC);
            rc = *reinterpret_cast<const uint4*>(gBh + (c + 1) * KC);
            rd = *reinterpret_cast<const uint4*>(gBl + (c + 1) * KC);
        }

        uint32_t baseAh = smem_u32(&sAh[cur][0]);
        uint32_t baseAl = smem_u32(&sAl[cur][0]);
        uint32_t baseBh = smem_u32(&sBh[cur][0]);
        uint32_t baseBl = smem_u32(&sBl[cur][0]);

        unsigned fA[4][4], fBh[4][2], fBl[4][2];
        #pragma unroll
        for (int np = 0; np < 2; np++) {
            unsigned r4[4];
            uint32_t ab = baseBh + (uint32_t)(b_row + np * 16) * (PAD * 2) + b_cb;
            ldm_x4(r4, ab);
            fBh[np * 2 + 0][0] = r4[0]; fBh[np * 2 + 0][1] = r4[1];
            fBh[np * 2 + 1][0] = r4[2]; fBh[np * 2 + 1][1] = r4[3];
            ab = baseBl + (uint32_t)(b_row + np * 16) * (PAD * 2) + b_cb;
            ldm_x4(r4, ab);
            fBl[np * 2 + 0][0] = r4[0]; fBl[np * 2 + 0][1] = r4[1];
            fBl[np * 2 + 1][0] = r4[2]; fBl[np * 2 + 1][1] = r4[3];
        }
        #pragma unroll
        for (int mt = 0; mt < 4; mt++)
            ldm_x4(fA[mt], baseAh + (uint32_t)(a_row + mt * 16) * (PAD * 2) + a_cb);
        #pragma unroll
        for (int mt = 0; mt < 4; mt++)
            #pragma unroll
            for (int nt = 0; nt < 4; nt++)
                mma_bf16(acc[mt][nt], fA[mt], fBh[nt]);
        #pragma unroll
        for (int mt = 0; mt < 4; mt++)
            #pragma unroll
            for (int nt = 0; nt < 4; nt++)
                mma_bf16(acc[mt][nt], fA[mt], fBl[nt]);
        #pragma unroll
        for (int mt = 0; mt < 4; mt++)
            ldm_x4(fA[mt], baseAl + (uint32_t)(a_row + mt * 16) * (PAD * 2) + a_cb);
        #pragma unroll
        for (int mt = 0; mt < 4; mt++)
            #pragma unroll
            for (int nt = 0; nt < 4; nt++)
                mma_bf16(acc[mt][nt], fA[mt], fBh[nt]);

        if (c + 1 < nch) {
            int nxt = cur ^ 1;
            *reinterpret_cast<uint4*>(&sAh[nxt][so]) = ra;
            *reinterpret_cast<uint4*>(&sAl[nxt][so]) = rb;
            *reinterpret_cast<uint4*>(&sBh[nxt][so]) = rc;
            *reinterpret_cast<uint4*>(&sBl[nxt][so]) = rd;
        }
        __syncthreads();
    }

    // epilogue
    #pragma unroll
    for (int mt = 0; mt < 4; mt++) {
        int row = m0 + wm * 64 + mt * 16 + (lane >> 2);
        #pragma unroll
        for (int nt = 0; nt < 4; nt++) {
            int col = n0 + wn * 32 + nt * 8 + (lane & 3) * 2;
            if (SPLIT) {
                float sc = (col < qcols) ? 0.125f : 1.0f;
                #pragma unroll
                for (int half = 0; half < 2; half++) {
                    int rr = row + half * 8;
                    float v0 = acc[mt][nt][half * 2 + 0] * sc;
                    float v1 = acc[mt][nt][half * 2 + 1] * sc;
                    unsigned hp = pack_bf2(v0, v1);
                    unsigned lp = pack_bf2(v0 - bf_round(v0), v1 - bf_round(v1));
                    *reinterpret_cast<unsigned*>(Ch + (size_t)rr * N + col) = hp;
                    *reinterpret_cast<unsigned*>(Cl + (size_t)rr * N + col) = lp;
                }
            } else {
                float bx = bias[col], by = bias[col + 1];
                float2 r0 = make_float2(acc[mt][nt][0] + bx, acc[mt][nt][1] + by);
                float2 r1 = make_float2(acc[mt][nt][2] + bx, acc[mt][nt][3] + by);
                *reinterpret_cast<float2*>(C + (size_t)row * N + col) = r0;
                *reinterpret_cast<float2*>(C + (size_t)(row + 8) * N + col) = r1;
            }
        }
    }
}

// ---------------------------------------------------------------------------
// Flash attention on tensor cores (bf16x3, FA2-style register softmax).
// BQ=128 (8 warps x 16 rows), BK=64, hd=64. Q pre-scaled by 0.125.
// ---------------------------------------------------------------------------
#define APAD 72

__global__ void __launch_bounds__(256)
attn_mma(const bf16* __restrict__ qkh, const bf16* __restrict__ qkl,
         const bf16* __restrict__ vh, const bf16* __restrict__ vl,
         float* __restrict__ out) {
    __shared__ bf16 sm[4 * 64 * APAD];   // Kh|Kl|Vh|Vl; also Q staging (256*APAD)

    int qt = blockIdx.x, h = blockIdx.y, b = blockIdx.z;
    int tid = threadIdx.x, warp = tid >> 5, lane = tid & 31;
    int quad = lane >> 2, tq = lane & 3;

    // --- stage Q hi/lo and build persistent A-frags ---
    for (int i = tid; i < 128 * 8; i += 256) {
        int r = i >> 3, c8 = (i & 7) * 8;
        size_t grow = (size_t)(b * NN + qt * 128 + r) * (2 * CC) + h * HD + c8;
        *reinterpret_cast<uint4*>(&sm[r * APAD + c8]) =
            *reinterpret_cast<const uint4*>(qkh + grow);
        *reinterpret_cast<uint4*>(&sm[(128 + r) * APAD + c8]) =
            *reinterpret_cast<const uint4*>(qkl + grow);
    }
    __syncthreads();
    unsigned fQh[4][4], fQl[4][4];
    {
        int ar = warp * 16 + (lane & 15);
        int cb = ((lane >> 4) & 1) * 16;
        #pragma unroll
        for (int kk = 0; kk < 4; kk++) {
            ldm_x4(fQh[kk], smem_u32(&sm[ar * APAD]) + kk * 32 + cb);
            ldm_x4(fQl[kk], smem_u32(&sm[(128 + ar) * APAD]) + kk * 32 + cb);
        }
    }
    __syncthreads();

    const uint32_t sKh = smem_u32(&sm[0]);
    const uint32_t sKl = sKh + 64 * APAD * 2;
    const uint32_t sVh = sKh + 2 * 64 * APAD * 2;
    const uint32_t sVl = sKh + 3 * 64 * APAD * 2;

    float O[8][4];
    #pragma unroll
    for (int nt = 0; nt < 8; nt++)
        #pragma unroll
        for (int q = 0; q < 4; q++) O[nt][q] = 0.0f;
    float m0 = -1e30f, m1 = -1e30f, l0 = 0.0f, l1 = 0.0f;

    // K/V gmem addressing (2 uint4 chunks per tensor per thread)
    int kr0 = tid >> 3, kc0 = (tid & 7) * 8;           // chunk tid
    int kr1 = (tid + 256) >> 3, kc1 = kc0;             // chunk tid+256

    // B-frag ldmatrix lane addressing
    int kb_row = ((lane >> 4) & 1) * 8 + (lane & 7);   // + np*16
    int kb_cb  = ((lane >> 3) & 1) * 16;               // + kk*32
    int vb_row = ((lane >> 3) & 1) * 8 + (lane & 7);   // + kk*16
    int vb_cb  = ((lane >> 4) & 1) * 16;               // + nt2*16

    uint4 pkh0, pkh1, pkl0, pkl1, pvh0, pvh1, pvl0, pvl1;
    {
        size_t g0 = (size_t)(b * NN + kr0) * (2 * CC) + CC + h * HD + kc0;
        size_t g1 = (size_t)(b * NN + kr1) * (2 * CC) + CC + h * HD + kc1;
        size_t v0 = (size_t)(b * NN + kr0) * CC + h * HD + kc0;
        size_t v1 = (size_t)(b * NN + kr1) * CC + h * HD + kc1;
        pkh0 = *reinterpret_cast<const uint4*>(qkh + g0);
        pkh1 = *reinterpret_cast<const uint4*>(qkh + g1);
        pkl0 = *reinterpret_cast<const uint4*>(qkl + g0);
        pkl1 = *reinterpret_cast<const uint4*>(qkl + g1);
        pvh0 = *reinterpret_cast<const uint4*>(vh + v0);
        pvh1 = *reinterpret_cast<const uint4*>(vh + v1);
        pvl0 = *reinterpret_cast<const uint4*>(vl + v0);
        pvl1 = *reinterpret_cast<const uint4*>(vl + v1);
    }

    #pragma unroll 1
    for (int it = 0; it < NN / 64; it++) {
        // store prefetched tile
        *reinterpret_cast<uint4*>(&sm[0 * 64 * APAD + kr0 * APAD + kc0]) = pkh0;
        *reinterpret_cast<uint4*>(&sm[0 * 64 * APAD + kr1 * APAD + kc1]) = pkh1;
        *reinterpret_cast<uint4*>(&sm[1 * 64 * APAD + kr0 * APAD + kc0]) = pkl0;
        *reinterpret_cast<uint4*>(&sm[1 * 64 * APAD + kr1 * APAD + kc1]) = pkl1;
        *reinterpret_cast<uint4*>(&sm[2 * 64 * APAD + kr0 * APAD + kc0]) = pvh0;
        *reinterpret_cast<uint4*>(&sm[2 * 64 * APAD + kr1 * APAD + kc1]) = pvh1;
        *reinterpret_cast<uint4*>(&sm[3 * 64 * APAD + kr0 * APAD + kc0]) = pvl0;
        *reinterpret_cast<uint4*>(&sm[3 * 64 * APAD + kr1 * APAD + kc1]) = pvl1;
        __syncthreads();

        if (it + 1 < NN / 64) {
            int k0 = (it + 1) * 64;
            size_t g0 = (size_t)(b * NN + k0 + kr0) * (2 * CC) + CC + h * HD + kc0;
            size_t g1 = (size_t)(b * NN + k0 + kr1) * (2 * CC) + CC + h * HD + kc1;
            size_t v0 = (size_t)(b * NN + k0 + kr0) * CC + h * HD + kc0;
            size_t v1 = (size_t)(b * NN + k0 + kr1) * CC + h * HD + kc1;
            pkh0 = *reinterpret_cast<const uint4*>(qkh + g0);
            pkh1 = *reinterpret_cast<const uint4*>(qkh + g1);
            pkl0 = *reinterpret_cast<const uint4*>(qkl + g0);
            pkl1 = *reinterpret_cast<const uint4*>(qkl + g1);
            pvh0 = *reinterpret_cast<const uint4*>(vh + v0);
            pvh1 = *reinterpret_cast<const uint4*>(vh + v1);
            pvl0 = *reinterpret_cast<const uint4*>(vl + v0);
            pvl1 = *reinterpret_cast<const uint4*>(vl + v1);
        }

        // ---- S = Q @ K^T (3 passes) ----
        float S[8][4];
        #pragma unroll
        for (int nt = 0; nt < 8; nt++)
            #pragma unroll
            for (int q = 0; q < 4; q++) S[nt][q] = 0.0f;

        #pragma unroll
        for (int kk = 0; kk < 4; kk++) {
            unsigned fKh[8][2], fKl[8][2];
            #pragma unroll
            for (int np = 0; np < 4; np++) {
                unsigned r4[4];
                uint32_t off = (uint32_t)(kb_row + np * 16) * (APAD * 2) + kb_cb + kk * 32;
                ldm_x4(r4, sKh + off);
                fKh[np * 2 + 0][0] = r4[0]; fKh[np * 2 + 0][1] = r4[1];
                fKh[np * 2 + 1][0] = r4[2]; fKh[np * 2 + 1][1] = r4[3];
                ldm_x4(r4, sKl + off);
                fKl[np * 2 + 0][0] = r4[0]; fKl[np * 2 + 0][1] = r4[1];
                fKl[np * 2 + 1][0] = r4[2]; fKl[np * 2 + 1][1] = r4[3];
            }
            #pragma unroll
            for (int nt = 0; nt < 8; nt++) {
                mma_bf16(S[nt], fQh[kk], fKh[nt]);
                mma_bf16(S[nt], fQh[kk], fKl[nt]);
                mma_bf16(S[nt], fQl[kk], fKh[nt]);
            }
        }

        // ---- online softmax in registers ----
        float mx0 = -1e30f, mx1 = -1e30f;
        #pragma unroll
        for (int nt = 0; nt < 8; nt++) {
            mx0 = fmaxf(mx0, fmaxf(S[nt][0], S[nt][1]));
            mx1 = fmaxf(mx1, fmaxf(S[nt][2], S[nt][3]));
        }
        mx0 = fmaxf(mx0, __shfl_xor_sync(0xFFFFFFFFu, mx0, 1));
        mx0 = fmaxf(mx0, __shfl_xor_sync(0xFFFFFFFFu, mx0, 2));
        mx1 = fmaxf(mx1, __shfl_xor_sync(0xFFFFFFFFu, mx1, 1));
        mx1 = fmaxf(mx1, __shfl_xor_sync(0xFFFFFFFFu, mx1, 2));
        float mn0 = fmaxf(m0, mx0), mn1 = fmaxf(m1, mx1);
        float al0 = __expf(m0 - mn0), al1 = __expf(m1 - mn1);
        m0 = mn0; m1 = mn1;

        float s0 = 0.0f, s1 = 0.0f;
        #pragma unroll
        for (int nt = 0; nt < 8; nt++) {
            S[nt][0] = __expf(S[nt][0] - mn0); s0 += S[nt][0];
            S[nt][1] = __expf(S[nt][1] - mn0); s0 += S[nt][1];
            S[nt][2] = __expf(S[nt][2] - mn1); s1 += S[nt][2];
            S[nt][3] = __expf(S[nt][3] - mn1); s1 += S[nt][3];
        }
        s0 += __shfl_xor_sync(0xFFFFFFFFu, s0, 1);
        s0 += __shfl_xor_sync(0xFFFFFFFFu, s0, 2);
        s1 += __shfl_xor_sync(0xFFFFFFFFu, s1, 1);
        s1 += __shfl_xor_sync(0xFFFFFFFFu, s1, 2);
        l0 = l0 * al0 + s0;
        l1 = l1 * al1 + s1;

        // rescale O
        #pragma unroll
        for (int nt = 0; nt < 8; nt++) {
            O[nt][0] *= al0; O[nt][1] *= al0;
            O[nt][2] *= al1; O[nt][3] *= al1;
        }

        // pack P hi/lo (C-frag -> A-frag identity)
        unsigned Phi[8][2], Plo[8][2];
        #pragma unroll
        for (int nt = 0; nt < 8; nt++) {
            float p0 = S[nt][0], p1 = S[nt][1], p2 = S[nt][2], p3 = S[nt][3];
            Phi[nt][0] = pack_bf2(p0, p1);
            Phi[nt][1] = pack_bf2(p2, p3);
            Plo[nt][0] = pack_bf2(p0 - bf_round(p0), p1 - bf_round(p1));
            Plo[nt][1] = pack_bf2(p2 - bf_round(p2), p3 - bf_round(p3));
        }

        // ---- O += P @ V (3 passes) ----
        #pragma unroll
        for (int kk = 0; kk < 4; kk++) {
            unsigned aPh[4] = {Phi[2 * kk][0], Phi[2 * kk][1],
                               Phi[2 * kk + 1][0], Phi[2 * kk + 1][1]};
            unsigned aPl[4] = {Plo[2 * kk][0], Plo[2 * kk][1],
                               Plo[2 * kk + 1][0], Plo[2 * kk + 1][1]};
            unsigned fVh[8][2], fVl[8][2];
            #pragma unroll
            for (int nt2 = 0; nt2 < 4; nt2++) {
                unsigned r4[4];
                uint32_t off = (uint32_t)(vb_row + kk * 16) * (APAD * 2) + vb_cb + nt2 * 32;
                ldm_x4t(r4, sVh + off);
                fVh[nt2 * 2 + 0][0] = r4[0]; fVh[nt2 * 2 + 0][1] = r4[1];
                fVh[nt2 * 2 + 1][0] = r4[2]; fVh[nt2 * 2 + 1][1] = r4[3];
                ldm_x4t(r4, sVl + off);
                fVl[nt2 * 2 + 0][0] = r4[0]; fVl[nt2 * 2 + 0][1] = r4[1];
                fVl[nt2 * 2 + 1][0] = r4[2]; fVl[nt2 * 2 + 1][1] = r4[3];
            }
            #pragma unroll
            for (int nt = 0; nt < 8; nt++) {
                mma_bf16(O[nt], aPh, fVh[nt]);
                mma_bf16(O[nt], aPh, fVl[nt]);
                mma_bf16(O[nt], aPl, fVh[nt]);
            }
        }
        __syncthreads();
    }

    // ---- finalize & store ----
    float inv0 = 1.0f / l0, inv1 = 1.0f / l1;
    int row0 = b * NN + qt * 128 + warp * 16 + quad;
    #pragma unroll
    for (int nt = 0; nt < 8; nt++) {
        int col = h * HD + nt * 8 + tq * 2;
        *reinterpret_cast<float2*>(out + (size_t)row0 * CC + col) =
            make_float2(O[nt][0] * inv0, O[nt][1] * inv0);
        *reinterpret_cast<float2*>(out + (size_t)(row0 + 8) * CC + col) =
            make_float2(O[nt][2] * inv1, O[nt][3] * inv1);
    }
}

// ---------------------------------------------------------------------------
extern "C" void kernel_launch(void* const* d_in, const int* in_sizes, int n_in,
                              void* d_out, int out_size) {
    const float* x      = (const float*)d_in[0];
    const float* ln1_g  = (const float*)d_in[1];
    const float* ln1_b  = (const float*)d_in[2];
    const float* w_qk   = (const float*)d_in[3];
    const float* w_v    = (const float*)d_in[4];
    const float* ln2_g  = (const float*)d_in[5];
    const float* ln2_b  = (const float*)d_in[6];
    const float* w_proj = (const float*)d_in[7];
    const float* b_proj = (const float*)d_in[8];
    float* out = (float*)d_out;

    float* ao;
    bf16 *xh, *xl, *qkh, *qkl, *vhp, *vlp, *wqkh, *wqkl, *wvh, *wvl, *wph, *wpl;
    cudaGetSymbolAddress((void**)&ao,   g_ao);
    cudaGetSymbolAddress((void**)&xh,   g_xh);
    cudaGetSymbolAddress((void**)&xl,   g_xl);
    cudaGetSymbolAddress((void**)&qkh,  g_qkh);
    cudaGetSymbolAddress((void**)&qkl,  g_qkl);
    cudaGetSymbolAddress((void**)&vhp,  g_vh);
    cudaGetSymbolAddress((void**)&vlp,  g_vl);
    cudaGetSymbolAddress((void**)&wqkh, g_wqkT_h);
    cudaGetSymbolAddress((void**)&wqkl, g_wqkT_l);
    cudaGetSymbolAddress((void**)&wvh,  g_wvT_h);
    cudaGetSymbolAddress((void**)&wvl,  g_wvT_l);
    cudaGetSymbolAddress((void**)&wph,  g_wpT_h);
    cudaGetSymbolAddress((void**)&wpl,  g_wpT_l);

    // weight transpose+split
    wsplit_kernel<<<dim3(2 * CC / 32, CC / 32), dim3(32, 8)>>>(w_qk, wqkh, wqkl, CC, 2 * CC);
    wsplit_kernel<<<dim3(CC / 32, CC / 32), dim3(32, 8)>>>(w_v, wvh, wvl, CC, CC);
    wsplit_kernel<<<dim3(CC / 32, CC / 32), dim3(32, 8)>>>(w_proj, wph, wpl, CC, CC);

    // 1. LN1 -> bf16 hi/lo
    ln_split_kernel<<<MM, 256>>>(x, ln1_g, ln1_b, xh, xl);

    // 2. projections -> bf16 hi/lo (q pre-scaled by 0.125)
    gemm_mma<true><<<dim3(2 * CC / 128, MM / 128), 256>>>(
        xh, xl, wqkh, wqkl, nullptr, nullptr, qkh, qkl, MM, 2 * CC, CC, CC);
    gemm_mma<true><<<dim3(CC / 128, MM / 128), 256>>>(
        xh, xl, wvh, wvl, nullptr, nullptr, vhp, vlp, MM, CC, CC, 0);

    // 3. tensor-core flash attention
    attn_mma<<<dim3(NN / 128, HH, BB), 256>>>(qkh, qkl, vhp, vlp, ao);

    // 4. LN2 -> bf16 hi/lo
    ln_split_kernel<<<MM, 256>>>(ao, ln2_g, ln2_b, xh, xl);

    // 5. output projection + bias (fp32 out)
    gemm_mma<false><<<dim3(CC / 128, MM / 128), 256>>>(
        xh, xl, wph, wpl, b_proj, out, nullptr, nullptr, MM, CC, CC, 0);
}